// round 14
// baseline (speedup 1.0000x reference)
#include <cuda_runtime.h>
#include <cuda_fp16.h>

#define N_NODES 100000
#define N_EDGES 1600000
#define N_GRAPHS 1024
#define H 64
#define L2E 1.4426950408889634f
#define EPS_L2E 1.4426950408889634e-7f
#define LN2F 0.6931471805599453f
#define NB_SCAN 98   // ceil(100000/1024)

typedef unsigned long long ull;

// ---------------- scratch (device globals; no allocation) ----------------
__device__ float  g_h[N_NODES * H];            // node features (ping)
__device__ float  g_mid[N_NODES * H];          // conv output before MLP (pong)
__device__ __half g_ea16[(size_t)N_EDGES * H]; // edge linear outputs, dst-sorted, fp16
__device__ int    g_src_sorted[N_EDGES];
__device__ int    g_deg[N_NODES];              // statically 0; re-zeroed by scatter each pass
__device__ int    g_off[N_NODES + 1];
__device__ int    g_cursor[N_NODES];
__device__ float  g_pool[N_GRAPHS * H];

// ---------------- intrinsics ----------------
__device__ __forceinline__ float ex2f(float x) {
    float y; asm("ex2.approx.ftz.f32 %0, %1;" : "=f"(y) : "f"(x)); return y;
}
__device__ __forceinline__ float rcpf(float x) {
    float y; asm("rcp.approx.ftz.f32 %0, %1;" : "=f"(y) : "f"(x)); return y;
}
__device__ __forceinline__ ull dup2(float x) {
    ull d; unsigned u = __float_as_uint(x);
    asm("mov.b64 %0, {%1, %1};" : "=l"(d) : "r"(u)); return d;
}
__device__ __forceinline__ void ffma2(ull& d, ull a, ull b) {
    asm("fma.rn.f32x2 %0, %1, %2, %0;" : "+l"(d) : "l"(a), "l"(b));
}
__device__ __forceinline__ float2 unpk(ull v) {
    float2 f; asm("mov.b64 {%0, %1}, %2;" : "=f"(f.x), "=f"(f.y) : "l"(v)); return f;
}

// ---------------- launch 1: node linear + dst histogram ----------------
__global__ void k_node_lin(const float* __restrict__ x,
                           const float* __restrict__ W,
                           const float* __restrict__ b,
                           const int* __restrict__ ei) {
    int gid = blockIdx.x * blockDim.x + threadIdx.x;
    if (gid < N_EDGES) atomicAdd(&g_deg[ei[N_EDGES + gid]], 1);

    __shared__ float sW[16 * 64];
    __shared__ float sb[64];
    int tid = threadIdx.x;
    for (int i = tid; i < 1024; i += blockDim.x) sW[i] = W[i];
    if (tid < 64) sb[tid] = b[tid];
    __syncthreads();
    int warp = gid >> 5;
    if (warp >= N_NODES) return;
    int lane = tid & 31;
    float xv = (lane < 16) ? x[(size_t)warp * 16 + lane] : 0.f;
    float ax = sb[2 * lane], ay = sb[2 * lane + 1];
#pragma unroll
    for (int k = 0; k < 16; k++) {
        float xk = __shfl_sync(0xffffffffu, xv, k);
        ax = fmaf(xk, sW[k * 64 + 2 * lane], ax);
        ay = fmaf(xk, sW[k * 64 + 2 * lane + 1], ay);
    }
    ((float2*)g_h)[(size_t)warp * 32 + lane] = make_float2(ax, ay);
}

// ---------------- launch 2: single-kernel exclusive scan ----------------
__global__ void k_scan() {
    __shared__ int sred[32];
    __shared__ int ws[32];
    __shared__ int s_base;
    int tid = threadIdx.x, lane = tid & 31, wid = tid >> 5;
    int limit = blockIdx.x << 10;
    int acc = 0;
    for (int j = tid; j < limit; j += 1024) acc += g_deg[j];
    for (int o = 16; o; o >>= 1) acc += __shfl_down_sync(0xffffffffu, acc, o);
    if (lane == 0) sred[wid] = acc;
    __syncthreads();
    if (tid < 32) {
        int a = sred[tid];
        for (int o = 16; o; o >>= 1) a += __shfl_down_sync(0xffffffffu, a, o);
        if (tid == 0) s_base = a;
    }
    int i = limit + tid;
    int v = (i < N_NODES) ? g_deg[i] : 0;
    int x = v;
#pragma unroll
    for (int d = 1; d < 32; d <<= 1) {
        int y = __shfl_up_sync(0xffffffffu, x, d);
        if (lane >= d) x += y;
    }
    if (lane == 31) ws[wid] = x;
    __syncthreads();
    if (wid == 0) {
        int w = ws[lane];
        int xx = w;
#pragma unroll
        for (int d = 1; d < 32; d <<= 1) {
            int y = __shfl_up_sync(0xffffffffu, xx, d);
            if (lane >= d) xx += y;
        }
        ws[lane] = xx - w;
    }
    __syncthreads();
    int ex = x - v + ws[wid] + s_base;
    if (i < N_NODES) { g_off[i] = ex; g_cursor[i] = ex; }
    if (i == 0) g_off[N_NODES] = N_EDGES;
}

// ---------------- launch 3: scatter, block-staged (256 edges/block) ----------
__global__ void __launch_bounds__(256) k_scatter(const int* __restrict__ ei,
                          const float* __restrict__ edge_attr,
                          const float* __restrict__ eW,
                          const float* __restrict__ eb) {
    __shared__ float s_attr[256 * 8];   // 8KB
    __shared__ int   s_pos[256];
    __shared__ float sW[8 * 64];
    __shared__ float sb[64];
    int tid = threadIdx.x;
    int gid = blockIdx.x * 256 + tid;
    if (gid < N_NODES) g_deg[gid] = 0;
    if (gid < N_GRAPHS * H) g_pool[gid] = 0.f;

    int e0 = blockIdx.x * 256;
    for (int i = tid; i < 512; i += 256) sW[i] = eW[i];
    if (tid < 64) sb[tid] = eb[tid];
    const float4* ga = (const float4*)(edge_attr + (size_t)e0 * 8);
    ((float4*)s_attr)[tid]       = ga[tid];
    ((float4*)s_attr)[tid + 256] = ga[tid + 256];
    int dst = ei[N_EDGES + e0 + tid];
    int pos = atomicAdd(&g_cursor[dst], 1);
    g_src_sorted[pos] = ei[e0 + tid];
    s_pos[tid] = pos;
    __syncthreads();

    int lane = tid & 31, w = tid >> 5;
    float2 Wr[8];
#pragma unroll
    for (int k = 0; k < 8; k++) Wr[k] = *(const float2*)&sW[k * 64 + 2 * lane];
    float bx = sb[2 * lane], by = sb[2 * lane + 1];
    const float* ap = s_attr + w * 32 * 8;
    const int* pp = s_pos + w * 32;
#pragma unroll 4
    for (int j = 0; j < 32; j++) {
        int p = pp[j];
        float4 a0 = *(const float4*)(ap + j * 8);
        float4 a1 = *(const float4*)(ap + j * 8 + 4);
        float ax = bx, ay = by;
        ax = fmaf(a0.x, Wr[0].x, ax); ay = fmaf(a0.x, Wr[0].y, ay);
        ax = fmaf(a0.y, Wr[1].x, ax); ay = fmaf(a0.y, Wr[1].y, ay);
        ax = fmaf(a0.z, Wr[2].x, ax); ay = fmaf(a0.z, Wr[2].y, ay);
        ax = fmaf(a0.w, Wr[3].x, ax); ay = fmaf(a0.w, Wr[3].y, ay);
        ax = fmaf(a1.x, Wr[4].x, ax); ay = fmaf(a1.x, Wr[4].y, ay);
        ax = fmaf(a1.y, Wr[5].x, ax); ay = fmaf(a1.y, Wr[5].y, ay);
        ax = fmaf(a1.z, Wr[6].x, ax); ay = fmaf(a1.z, Wr[6].y, ay);
        ax = fmaf(a1.w, Wr[7].x, ax); ay = fmaf(a1.w, Wr[7].y, ay);
        ((__half2*)g_ea16)[p * 32 + lane] = __floats2half2_rn(ax, ay);
    }
}

// ---------------- launch 4 (profiled): conv, 2 warps per node ----------------
// Block = 256 thr = 8 warps = 4 nodes. Warp pair (2i, 2i+1) shares node i's
// edge list: 8 quarter-warp groups stride edges by 8 (vs 4), halving each
// warp's serial chain. Odd warp's partial (s1,s2) merged via smem (no max
// state -> plain adds). Grid = N_NODES/4 = 25000 exactly.
__global__ void __launch_bounds__(256, 5) k_conv() {
    __shared__ float smrg[4][128];   // odd warp partials: [pair][s1(64)|s2(64)]
    int tid = threadIdx.x;
    int w = tid >> 5, lane = tid & 31;
    int pair = w >> 1;
    int node = blockIdx.x * 4 + pair;
    int L8 = (lane & 7) * 8;                   // first of 8 owned features
    int grp = ((w & 1) << 2) | (lane >> 3);    // 0..7
    int beg = g_off[node], end = g_off[node + 1];

    const float*  hbase = g_h + L8;
    const __half* ebase = g_ea16 + L8;

    float s1[8] = {0.f, 0.f, 0.f, 0.f, 0.f, 0.f, 0.f, 0.f};
    float s2[8] = {0.f, 0.f, 0.f, 0.f, 0.f, 0.f, 0.f, 0.f};

    for (int e = beg + grp; e < end; e += 8) {
        int sj = __ldg(&g_src_sorted[e]);
        const float4* hp = (const float4*)(hbase + sj * 64);
        float4 h0 = __ldg(hp);
        float4 h1 = __ldg(hp + 1);
        uint4 eab = __ldcs((const uint4*)(ebase + e * 64));
        float2 e0 = __half22float2(*(__half2*)&eab.x);
        float2 e1 = __half22float2(*(__half2*)&eab.y);
        float2 e2 = __half22float2(*(__half2*)&eab.z);
        float2 e3 = __half22float2(*(__half2*)&eab.w);
        float xs[8];
        xs[0] = fmaf(fmaxf(h0.x + e0.x, 0.f), L2E, EPS_L2E);
        xs[1] = fmaf(fmaxf(h0.y + e0.y, 0.f), L2E, EPS_L2E);
        xs[2] = fmaf(fmaxf(h0.z + e1.x, 0.f), L2E, EPS_L2E);
        xs[3] = fmaf(fmaxf(h0.w + e1.y, 0.f), L2E, EPS_L2E);
        xs[4] = fmaf(fmaxf(h1.x + e2.x, 0.f), L2E, EPS_L2E);
        xs[5] = fmaf(fmaxf(h1.y + e2.y, 0.f), L2E, EPS_L2E);
        xs[6] = fmaf(fmaxf(h1.z + e3.x, 0.f), L2E, EPS_L2E);
        xs[7] = fmaf(fmaxf(h1.w + e3.y, 0.f), L2E, EPS_L2E);
#pragma unroll
        for (int f = 0; f < 8; f++) {
            float tt = ex2f(xs[f]);
            s1[f] += tt;
            s2[f] = fmaf(xs[f], tt, s2[f]);   // scaled-x accumulation
        }
    }
    // intra-warp merge across the warp's 4 groups
#pragma unroll
    for (int f = 0; f < 8; f++) {
        s1[f] += __shfl_xor_sync(0xffffffffu, s1[f], 8);
        s2[f] += __shfl_xor_sync(0xffffffffu, s2[f], 8);
        s1[f] += __shfl_xor_sync(0xffffffffu, s1[f], 16);
        s2[f] += __shfl_xor_sync(0xffffffffu, s2[f], 16);
    }
    // odd warp publishes partials
    if ((w & 1) && lane < 8) {
        float* p1 = &smrg[pair][L8];
        float* p2 = &smrg[pair][64 + L8];
#pragma unroll
        for (int f = 0; f < 8; f++) { p1[f] = s1[f]; p2[f] = s2[f]; }
    }
    __syncthreads();
    // even warp merges partner + finalizes
    if (!(w & 1) && lane < 8) {
        const float* p1 = &smrg[pair][L8];
        const float* p2 = &smrg[pair][64 + L8];
#pragma unroll
        for (int f = 0; f < 8; f++) { s1[f] += p1[f]; s2[f] += p2[f]; }
        const float* hp = g_h + node * 64 + L8;
        float4 a0 = *(const float4*)hp;
        float4 a1 = *(const float4*)(hp + 4);
        float o[8];
#pragma unroll
        for (int f = 0; f < 8; f++)
            o[f] = (s1[f] > 0.f) ? s2[f] * rcpf(s1[f]) * LN2F : 0.f;
        float4 w0 = make_float4(a0.x + o[0], a0.y + o[1], a0.z + o[2], a0.w + o[3]);
        float4 w1 = make_float4(a1.x + o[4], a1.y + o[5], a1.z + o[6], a1.w + o[7]);
        float* mp = g_mid + node * 64 + L8;
        *(float4*)mp = w0;
        *(float4*)(mp + 4) = w1;
    }
}

// ---------------- fused 2-layer MLP (R6 proven form + pooled last layer) -----
__global__ void __launch_bounds__(256, 2)
k_mlp(const float* __restrict__ W1, const float* __restrict__ b1,
      const float* __restrict__ W2, const float* __restrict__ b2,
      const int* __restrict__ batch, int last) {
    extern __shared__ float sm[];
    float* A   = sm;           // [128][64]
    float* W1s = sm + 8192;    // [64][128]
    float* W2s = sm + 16384;   // [128][64]
    int tid = threadIdx.x;
    int block0 = blockIdx.x * 128;
    float4 z4 = make_float4(0.f, 0.f, 0.f, 0.f);
    for (int i = tid; i < 2048; i += 256) {
        int node = block0 + (i >> 4);
        ((float4*)A)[i] = (node < N_NODES)
            ? __ldcs(((const float4*)g_mid) + (size_t)block0 * 16 + i) : z4;
    }
    for (int i = tid; i < 2048; i += 256) ((float4*)W1s)[i] = ((const float4*)W1)[i];
    for (int i = tid; i < 2048; i += 256) ((float4*)W2s)[i] = ((const float4*)W2)[i];
    __syncthreads();

    int tx = tid & 15, ty = tid >> 4;
    int r0 = ty * 8, c0 = tx * 8;

    ull acc[8][4];
#pragma unroll
    for (int i = 0; i < 8; i++)
#pragma unroll
        for (int p = 0; p < 4; p++) acc[i][p] = 0ull;

    for (int k = 0; k < 64; k += 4) {
#pragma unroll
        for (int half = 0; half < 2; half++) {
            float ac[4][4];
#pragma unroll
            for (int i = 0; i < 4; i++) {
                float4 a4 = *(const float4*)(A + (r0 + half * 4 + i) * 64 + k);
                ac[i][0] = a4.x; ac[i][1] = a4.y; ac[i][2] = a4.z; ac[i][3] = a4.w;
            }
#pragma unroll
            for (int kk = 0; kk < 4; kk++) {
                ulonglong2 q0 = *(const ulonglong2*)(W1s + (k + kk) * 128 + c0);
                ulonglong2 q1 = *(const ulonglong2*)(W1s + (k + kk) * 128 + c0 + 4);
#pragma unroll
                for (int i = 0; i < 4; i++) {
                    ull ad = dup2(ac[i][kk]);
                    int ii = half * 4 + i;
                    ffma2(acc[ii][0], ad, q0.x);
                    ffma2(acc[ii][1], ad, q0.y);
                    ffma2(acc[ii][2], ad, q1.x);
                    ffma2(acc[ii][3], ad, q1.y);
                }
            }
        }
    }
    float bb[8];
#pragma unroll
    for (int j = 0; j < 8; j++) bb[j] = b1[c0 + j];
    __syncthreads();  // all A/W1s reads done; hid overlays sm[0..16384)
#pragma unroll
    for (int i = 0; i < 8; i++) {
        float2 u0 = unpk(acc[i][0]), u1 = unpk(acc[i][1]);
        float2 u2 = unpk(acc[i][2]), u3 = unpk(acc[i][3]);
        float4 f0, f1;
        f0.x = fmaxf(u0.x + bb[0], 0.f); f0.y = fmaxf(u0.y + bb[1], 0.f);
        f0.z = fmaxf(u1.x + bb[2], 0.f); f0.w = fmaxf(u1.y + bb[3], 0.f);
        f1.x = fmaxf(u2.x + bb[4], 0.f); f1.y = fmaxf(u2.y + bb[5], 0.f);
        f1.z = fmaxf(u3.x + bb[6], 0.f); f1.w = fmaxf(u3.y + bb[7], 0.f);
        *(float4*)(sm + (r0 + i) * 128 + c0) = f0;
        *(float4*)(sm + (r0 + i) * 128 + c0 + 4) = f1;
    }
    __syncthreads();

    int ty2 = tid >> 3, tx2 = tid & 7;
    int rr = ty2 * 4, cc = tx2 * 8;
    ull acc2[4][4];
#pragma unroll
    for (int i = 0; i < 4; i++)
#pragma unroll
        for (int p = 0; p < 4; p++) acc2[i][p] = 0ull;

    for (int k = 0; k < 128; k += 4) {
        float ac[4][4];
#pragma unroll
        for (int i = 0; i < 4; i++) {
            float4 a4 = *(const float4*)(sm + (rr + i) * 128 + k);
            ac[i][0] = a4.x; ac[i][1] = a4.y; ac[i][2] = a4.z; ac[i][3] = a4.w;
        }
#pragma unroll
        for (int kk = 0; kk < 4; kk++) {
            ulonglong2 q0 = *(const ulonglong2*)(W2s + (k + kk) * 64 + cc);
            ulonglong2 q1 = *(const ulonglong2*)(W2s + (k + kk) * 64 + cc + 4);
#pragma unroll
            for (int i = 0; i < 4; i++) {
                ull ad = dup2(ac[i][kk]);
                ffma2(acc2[i][0], ad, q0.x);
                ffma2(acc2[i][1], ad, q0.y);
                ffma2(acc2[i][2], ad, q1.x);
                ffma2(acc2[i][3], ad, q1.y);
            }
        }
    }
    float b2v[8];
#pragma unroll
    for (int j = 0; j < 8; j++) b2v[j] = b2[cc + j];
#pragma unroll
    for (int i = 0; i < 4; i++) {
        int node = block0 + rr + i;
        if (node < N_NODES) {
            float2 u0 = unpk(acc2[i][0]), u1 = unpk(acc2[i][1]);
            float2 u2 = unpk(acc2[i][2]), u3 = unpk(acc2[i][3]);
            float4 f0, f1;
            f0.x = fmaxf(u0.x + b2v[0], 0.f); f0.y = fmaxf(u0.y + b2v[1], 0.f);
            f0.z = fmaxf(u1.x + b2v[2], 0.f); f0.w = fmaxf(u1.y + b2v[3], 0.f);
            f1.x = fmaxf(u2.x + b2v[4], 0.f); f1.y = fmaxf(u2.y + b2v[5], 0.f);
            f1.z = fmaxf(u3.x + b2v[6], 0.f); f1.w = fmaxf(u3.y + b2v[7], 0.f);
            if (!last) {
                float* hp = g_h + (size_t)node * 64 + cc;
                *(float4*)hp = f0;
                *(float4*)(hp + 4) = f1;
            } else {
                int g = __ldg(&batch[node]);
                float* pp = g_pool + g * 64 + cc;
                atomicAdd(pp + 0, f0.x); atomicAdd(pp + 1, f0.y);
                atomicAdd(pp + 2, f0.z); atomicAdd(pp + 3, f0.w);
                atomicAdd(pp + 4, f1.x); atomicAdd(pp + 5, f1.y);
                atomicAdd(pp + 6, f1.z); atomicAdd(pp + 7, f1.w);
            }
        }
    }
}

// ---------------- head: cnt via binary search on sorted batch ----------------
__global__ void k_head(const float* __restrict__ gattr,
                       const int* __restrict__ batch,
                       const float* __restrict__ d1W, const float* __restrict__ d1b,
                       const float* __restrict__ d2W, const float* __restrict__ d2b,
                       const float* __restrict__ oW, const float* __restrict__ ob,
                       float* __restrict__ out) {
    int g = blockIdx.x;
    int lane = threadIdx.x;
    __shared__ float gv[80];
    __shared__ float h1[32];
    __shared__ float h2s[32];
    int lb = 0;
    if (lane < 2) {
        int target = g + lane;
        int lo = 0, hi = N_NODES;
        while (lo < hi) {
            int mid = (lo + hi) >> 1;
            if (__ldg(&batch[mid]) < target) lo = mid + 1; else hi = mid;
        }
        lb = lo;
    }
    int cb = __shfl_sync(0xffffffffu, lb, 0);
    int ce = __shfl_sync(0xffffffffu, lb, 1);
    float inv = rcpf(fmaxf((float)(ce - cb), 1.0f));
    gv[lane] = g_pool[g * 64 + lane] * inv;
    gv[32 + lane] = g_pool[g * 64 + 32 + lane] * inv;
    if (lane < 10) gv[64 + lane] = gattr[g * 10 + lane];
    __syncwarp();
    float acc = d1b[lane];
#pragma unroll
    for (int k = 0; k < 74; k++) acc = fmaf(gv[k], d1W[k * 32 + lane], acc);
    h1[lane] = fmaxf(acc, 0.f);
    __syncwarp();
    acc = d2b[lane];
#pragma unroll
    for (int k = 0; k < 32; k++) acc = fmaf(h1[k], d2W[k * 32 + lane], acc);
    h2s[lane] = fmaxf(acc, 0.f);
    __syncwarp();
    float p = h2s[lane] * oW[lane];
    for (int o = 16; o; o >>= 1) p += __shfl_down_sync(0xffffffffu, p, o);
    if (lane == 0) {
        float z = p + ob[0];
        out[g] = rcpf(1.0f + ex2f(-z * L2E));
    }
}

// ---------------- launcher ----------------
extern "C" void kernel_launch(void* const* d_in, const int* in_sizes, int n_in,
                              void* d_out, int out_size) {
    const float* ord[25];
    const int* edge_index = nullptr;
    const int* batch = nullptr;
    int w = 0;
    for (int i = 0; i < n_in; i++) {
        if (in_sizes[i] == 2 * N_EDGES) edge_index = (const int*)d_in[i];
        else if (in_sizes[i] == N_NODES) batch = (const int*)d_in[i];
        else if (w < 25) ord[w++] = (const float*)d_in[i];
    }
    const float* x        = ord[0];
    const float* edge_at  = ord[1];
    const float* gattr    = ord[2];
    const float* node_W   = ord[3];
    const float* node_b   = ord[4];
    const float* edge_W   = ord[5];
    const float* edge_b   = ord[6];
    const float* cW1[3]   = {ord[7],  ord[11], ord[15]};
    const float* cb1[3]   = {ord[8],  ord[12], ord[16]};
    const float* cW2[3]   = {ord[9],  ord[13], ord[17]};
    const float* cb2[3]   = {ord[10], ord[14], ord[18]};
    const float* d1W = ord[19]; const float* d1b = ord[20];
    const float* d2W = ord[21]; const float* d2b = ord[22];
    const float* oW  = ord[23]; const float* ob  = ord[24];

    cudaFuncSetAttribute(k_mlp, cudaFuncAttributeMaxDynamicSharedMemorySize, 98304);

    k_node_lin<<<(N_NODES + 7) / 8, 256>>>(x, node_W, node_b, edge_index); // 1
    k_scan<<<NB_SCAN, 1024>>>();                                           // 2
    k_scatter<<<N_EDGES / 256, 256>>>(edge_index, edge_at, edge_W, edge_b); // 3

    for (int c = 0; c < 3; c++) {
        k_conv<<<N_NODES / 4, 256>>>();   // 4 on first iter = profiled
        k_mlp<<<(N_NODES + 127) / 128, 256, 98304>>>(cW1[c], cb1[c], cW2[c], cb2[c],
                                                     batch, c == 2);
    }

    k_head<<<N_GRAPHS, 32>>>(gattr, batch, d1W, d1b, d2W, d2b, oW, ob, (float*)d_out);
    (void)out_size;
}

// round 15
// speedup vs baseline: 1.1064x; 1.1064x over previous
#include <cuda_runtime.h>
#include <cuda_fp16.h>

#define N_NODES 100000
#define N_EDGES 1600000
#define N_GRAPHS 1024
#define H 64
#define L2E 1.4426950408889634f
#define EPS_L2E 1.4426950408889634e-7f
#define LN2F 0.6931471805599453f
#define NB_SCAN 98   // ceil(100000/1024)

typedef unsigned long long ull;

// ---------------- scratch (device globals; no allocation) ----------------
__device__ float  g_h[N_NODES * H];            // node features fp32 (ping)
__device__ __half g_h16[N_NODES * H];          // fp16 mirror of g_h (conv gather)
__device__ float  g_mid[N_NODES * H];          // conv output before MLP (pong)
__device__ __half g_ea16[(size_t)N_EDGES * H]; // edge linear outputs, dst-sorted, fp16
__device__ int    g_src_sorted[N_EDGES];
__device__ int    g_deg[N_NODES];              // statically 0; re-zeroed by scatter each pass
__device__ int    g_off[N_NODES + 1];
__device__ int    g_cursor[N_NODES];
__device__ float  g_pool[N_GRAPHS * H];

// ---------------- intrinsics ----------------
__device__ __forceinline__ float ex2f(float x) {
    float y; asm("ex2.approx.ftz.f32 %0, %1;" : "=f"(y) : "f"(x)); return y;
}
__device__ __forceinline__ float rcpf(float x) {
    float y; asm("rcp.approx.ftz.f32 %0, %1;" : "=f"(y) : "f"(x)); return y;
}
__device__ __forceinline__ ull dup2(float x) {
    ull d; unsigned u = __float_as_uint(x);
    asm("mov.b64 %0, {%1, %1};" : "=l"(d) : "r"(u)); return d;
}
__device__ __forceinline__ void ffma2(ull& d, ull a, ull b) {
    asm("fma.rn.f32x2 %0, %1, %2, %0;" : "+l"(d) : "l"(a), "l"(b));
}
__device__ __forceinline__ float2 unpk(ull v) {
    float2 f; asm("mov.b64 {%0, %1}, %2;" : "=f"(f.x), "=f"(f.y) : "l"(v)); return f;
}

// ---------------- launch 1: node linear + dst histogram ----------------
__global__ void k_node_lin(const float* __restrict__ x,
                           const float* __restrict__ W,
                           const float* __restrict__ b,
                           const int* __restrict__ ei) {
    int gid = blockIdx.x * blockDim.x + threadIdx.x;
    if (gid < N_EDGES) atomicAdd(&g_deg[ei[N_EDGES + gid]], 1);

    __shared__ float sW[16 * 64];
    __shared__ float sb[64];
    int tid = threadIdx.x;
    for (int i = tid; i < 1024; i += blockDim.x) sW[i] = W[i];
    if (tid < 64) sb[tid] = b[tid];
    __syncthreads();
    int warp = gid >> 5;
    if (warp >= N_NODES) return;
    int lane = tid & 31;
    float xv = (lane < 16) ? x[(size_t)warp * 16 + lane] : 0.f;
    float ax = sb[2 * lane], ay = sb[2 * lane + 1];
#pragma unroll
    for (int k = 0; k < 16; k++) {
        float xk = __shfl_sync(0xffffffffu, xv, k);
        ax = fmaf(xk, sW[k * 64 + 2 * lane], ax);
        ay = fmaf(xk, sW[k * 64 + 2 * lane + 1], ay);
    }
    ((float2*)g_h)[(size_t)warp * 32 + lane] = make_float2(ax, ay);
    ((__half2*)g_h16)[(size_t)warp * 32 + lane] = __floats2half2_rn(ax, ay);
}

// ---------------- launch 2: single-kernel exclusive scan ----------------
__global__ void k_scan() {
    __shared__ int sred[32];
    __shared__ int ws[32];
    __shared__ int s_base;
    int tid = threadIdx.x, lane = tid & 31, wid = tid >> 5;
    int limit = blockIdx.x << 10;
    int acc = 0;
    for (int j = tid; j < limit; j += 1024) acc += g_deg[j];
    for (int o = 16; o; o >>= 1) acc += __shfl_down_sync(0xffffffffu, acc, o);
    if (lane == 0) sred[wid] = acc;
    __syncthreads();
    if (tid < 32) {
        int a = sred[tid];
        for (int o = 16; o; o >>= 1) a += __shfl_down_sync(0xffffffffu, a, o);
        if (tid == 0) s_base = a;
    }
    int i = limit + tid;
    int v = (i < N_NODES) ? g_deg[i] : 0;
    int x = v;
#pragma unroll
    for (int d = 1; d < 32; d <<= 1) {
        int y = __shfl_up_sync(0xffffffffu, x, d);
        if (lane >= d) x += y;
    }
    if (lane == 31) ws[wid] = x;
    __syncthreads();
    if (wid == 0) {
        int w = ws[lane];
        int xx = w;
#pragma unroll
        for (int d = 1; d < 32; d <<= 1) {
            int y = __shfl_up_sync(0xffffffffu, xx, d);
            if (lane >= d) xx += y;
        }
        ws[lane] = xx - w;
    }
    __syncthreads();
    int ex = x - v + ws[wid] + s_base;
    if (i < N_NODES) { g_off[i] = ex; g_cursor[i] = ex; }
    if (i == 0) g_off[N_NODES] = N_EDGES;
}

// ---------------- launch 3: scatter, block-staged (256 edges/block) ----------
__global__ void __launch_bounds__(256) k_scatter(const int* __restrict__ ei,
                          const float* __restrict__ edge_attr,
                          const float* __restrict__ eW,
                          const float* __restrict__ eb) {
    __shared__ float s_attr[256 * 8];   // 8KB
    __shared__ int   s_pos[256];
    __shared__ float sW[8 * 64];
    __shared__ float sb[64];
    int tid = threadIdx.x;
    int gid = blockIdx.x * 256 + tid;
    if (gid < N_NODES) g_deg[gid] = 0;
    if (gid < N_GRAPHS * H) g_pool[gid] = 0.f;

    int e0 = blockIdx.x * 256;
    for (int i = tid; i < 512; i += 256) sW[i] = eW[i];
    if (tid < 64) sb[tid] = eb[tid];
    const float4* ga = (const float4*)(edge_attr + (size_t)e0 * 8);
    ((float4*)s_attr)[tid]       = ga[tid];
    ((float4*)s_attr)[tid + 256] = ga[tid + 256];
    int dst = ei[N_EDGES + e0 + tid];
    int pos = atomicAdd(&g_cursor[dst], 1);
    g_src_sorted[pos] = ei[e0 + tid];
    s_pos[tid] = pos;
    __syncthreads();

    int lane = tid & 31, w = tid >> 5;
    float2 Wr[8];
#pragma unroll
    for (int k = 0; k < 8; k++) Wr[k] = *(const float2*)&sW[k * 64 + 2 * lane];
    float bx = sb[2 * lane], by = sb[2 * lane + 1];
    const float* ap = s_attr + w * 32 * 8;
    const int* pp = s_pos + w * 32;
#pragma unroll 4
    for (int j = 0; j < 32; j++) {
        int p = pp[j];
        float4 a0 = *(const float4*)(ap + j * 8);
        float4 a1 = *(const float4*)(ap + j * 8 + 4);
        float ax = bx, ay = by;
        ax = fmaf(a0.x, Wr[0].x, ax); ay = fmaf(a0.x, Wr[0].y, ay);
        ax = fmaf(a0.y, Wr[1].x, ax); ay = fmaf(a0.y, Wr[1].y, ay);
        ax = fmaf(a0.z, Wr[2].x, ax); ay = fmaf(a0.z, Wr[2].y, ay);
        ax = fmaf(a0.w, Wr[3].x, ax); ay = fmaf(a0.w, Wr[3].y, ay);
        ax = fmaf(a1.x, Wr[4].x, ax); ay = fmaf(a1.x, Wr[4].y, ay);
        ax = fmaf(a1.y, Wr[5].x, ax); ay = fmaf(a1.y, Wr[5].y, ay);
        ax = fmaf(a1.z, Wr[6].x, ax); ay = fmaf(a1.z, Wr[6].y, ay);
        ax = fmaf(a1.w, Wr[7].x, ax); ay = fmaf(a1.w, Wr[7].y, ay);
        ((__half2*)g_ea16)[p * 32 + lane] = __floats2half2_rn(ax, ay);
    }
}

// ---------------- launch 4 (profiled): conv, fp16 gather + half2 math --------
// Warp per node, quarter-warp groups stride edges by 4 (R6 schedule).
// h gathered from fp16 mirror (1 LDG.128); relu(h+ea) in half2; exp in fp32.
__global__ void __launch_bounds__(256, 5) k_conv() {
    int warp = (blockIdx.x * blockDim.x + threadIdx.x) >> 5;
    if (warp >= N_NODES) return;
    int lane = threadIdx.x & 31;
    int L8 = (lane & 7) * 8;    // first of 8 owned features
    int grp = lane >> 3;        // edge slot within step
    int beg = g_off[warp], end = g_off[warp + 1];

    const __half* hbase = g_h16 + L8;
    const __half* ebase = g_ea16 + L8;
    const __half2 z2 = __float2half2_rn(0.f);

    float s1[8] = {0.f, 0.f, 0.f, 0.f, 0.f, 0.f, 0.f, 0.f};
    float s2[8] = {0.f, 0.f, 0.f, 0.f, 0.f, 0.f, 0.f, 0.f};

    for (int e = beg + grp; e < end; e += 4) {
        int sj = __ldg(&g_src_sorted[e]);
        uint4 hr = __ldg((const uint4*)(hbase + sj * 64));
        uint4 er = __ldcs((const uint4*)(ebase + e * 64));
        __half2 m0 = __hmax2(__hadd2(*(__half2*)&hr.x, *(__half2*)&er.x), z2);
        __half2 m1 = __hmax2(__hadd2(*(__half2*)&hr.y, *(__half2*)&er.y), z2);
        __half2 m2 = __hmax2(__hadd2(*(__half2*)&hr.z, *(__half2*)&er.z), z2);
        __half2 m3 = __hmax2(__hadd2(*(__half2*)&hr.w, *(__half2*)&er.w), z2);
        float2 f0 = __half22float2(m0);
        float2 f1 = __half22float2(m1);
        float2 f2 = __half22float2(m2);
        float2 f3 = __half22float2(m3);
        float xs[8];
        xs[0] = fmaf(f0.x, L2E, EPS_L2E);
        xs[1] = fmaf(f0.y, L2E, EPS_L2E);
        xs[2] = fmaf(f1.x, L2E, EPS_L2E);
        xs[3] = fmaf(f1.y, L2E, EPS_L2E);
        xs[4] = fmaf(f2.x, L2E, EPS_L2E);
        xs[5] = fmaf(f2.y, L2E, EPS_L2E);
        xs[6] = fmaf(f3.x, L2E, EPS_L2E);
        xs[7] = fmaf(f3.y, L2E, EPS_L2E);
#pragma unroll
        for (int f = 0; f < 8; f++) {
            float tt = ex2f(xs[f]);
            s1[f] += tt;
            s2[f] = fmaf(xs[f], tt, s2[f]);   // scaled-x accumulation
        }
    }
#pragma unroll
    for (int f = 0; f < 8; f++) {
        s1[f] += __shfl_xor_sync(0xffffffffu, s1[f], 8);
        s2[f] += __shfl_xor_sync(0xffffffffu, s2[f], 8);
        s1[f] += __shfl_xor_sync(0xffffffffu, s1[f], 16);
        s2[f] += __shfl_xor_sync(0xffffffffu, s2[f], 16);
    }
    if (lane < 8) {
        const float* hp = g_h + warp * 64 + L8;   // root add in fp32
        float4 a0 = *(const float4*)hp;
        float4 a1 = *(const float4*)(hp + 4);
        float o[8];
#pragma unroll
        for (int f = 0; f < 8; f++)
            o[f] = (s1[f] > 0.f) ? s2[f] * rcpf(s1[f]) * LN2F : 0.f;
        float4 w0 = make_float4(a0.x + o[0], a0.y + o[1], a0.z + o[2], a0.w + o[3]);
        float4 w1 = make_float4(a1.x + o[4], a1.y + o[5], a1.z + o[6], a1.w + o[7]);
        float* mp = g_mid + warp * 64 + L8;
        *(float4*)mp = w0;
        *(float4*)(mp + 4) = w1;
    }
}

// ---------------- fused 2-layer MLP (R6 proven form + pooled last layer) -----
// Non-last layers also write the fp16 mirror g_h16 for the next conv's gather.
__global__ void __launch_bounds__(256, 2)
k_mlp(const float* __restrict__ W1, const float* __restrict__ b1,
      const float* __restrict__ W2, const float* __restrict__ b2,
      const int* __restrict__ batch, int last) {
    extern __shared__ float sm[];
    float* A   = sm;           // [128][64]
    float* W1s = sm + 8192;    // [64][128]
    float* W2s = sm + 16384;   // [128][64]
    int tid = threadIdx.x;
    int block0 = blockIdx.x * 128;
    float4 z4 = make_float4(0.f, 0.f, 0.f, 0.f);
    for (int i = tid; i < 2048; i += 256) {
        int node = block0 + (i >> 4);
        ((float4*)A)[i] = (node < N_NODES)
            ? __ldcs(((const float4*)g_mid) + (size_t)block0 * 16 + i) : z4;
    }
    for (int i = tid; i < 2048; i += 256) ((float4*)W1s)[i] = ((const float4*)W1)[i];
    for (int i = tid; i < 2048; i += 256) ((float4*)W2s)[i] = ((const float4*)W2)[i];
    __syncthreads();

    int tx = tid & 15, ty = tid >> 4;
    int r0 = ty * 8, c0 = tx * 8;

    ull acc[8][4];
#pragma unroll
    for (int i = 0; i < 8; i++)
#pragma unroll
        for (int p = 0; p < 4; p++) acc[i][p] = 0ull;

    for (int k = 0; k < 64; k += 4) {
#pragma unroll
        for (int half = 0; half < 2; half++) {
            float ac[4][4];
#pragma unroll
            for (int i = 0; i < 4; i++) {
                float4 a4 = *(const float4*)(A + (r0 + half * 4 + i) * 64 + k);
                ac[i][0] = a4.x; ac[i][1] = a4.y; ac[i][2] = a4.z; ac[i][3] = a4.w;
            }
#pragma unroll
            for (int kk = 0; kk < 4; kk++) {
                ulonglong2 q0 = *(const ulonglong2*)(W1s + (k + kk) * 128 + c0);
                ulonglong2 q1 = *(const ulonglong2*)(W1s + (k + kk) * 128 + c0 + 4);
#pragma unroll
                for (int i = 0; i < 4; i++) {
                    ull ad = dup2(ac[i][kk]);
                    int ii = half * 4 + i;
                    ffma2(acc[ii][0], ad, q0.x);
                    ffma2(acc[ii][1], ad, q0.y);
                    ffma2(acc[ii][2], ad, q1.x);
                    ffma2(acc[ii][3], ad, q1.y);
                }
            }
        }
    }
    float bb[8];
#pragma unroll
    for (int j = 0; j < 8; j++) bb[j] = b1[c0 + j];
    __syncthreads();  // all A/W1s reads done; hid overlays sm[0..16384)
#pragma unroll
    for (int i = 0; i < 8; i++) {
        float2 u0 = unpk(acc[i][0]), u1 = unpk(acc[i][1]);
        float2 u2 = unpk(acc[i][2]), u3 = unpk(acc[i][3]);
        float4 f0, f1;
        f0.x = fmaxf(u0.x + bb[0], 0.f); f0.y = fmaxf(u0.y + bb[1], 0.f);
        f0.z = fmaxf(u1.x + bb[2], 0.f); f0.w = fmaxf(u1.y + bb[3], 0.f);
        f1.x = fmaxf(u2.x + bb[4], 0.f); f1.y = fmaxf(u2.y + bb[5], 0.f);
        f1.z = fmaxf(u3.x + bb[6], 0.f); f1.w = fmaxf(u3.y + bb[7], 0.f);
        *(float4*)(sm + (r0 + i) * 128 + c0) = f0;
        *(float4*)(sm + (r0 + i) * 128 + c0 + 4) = f1;
    }
    __syncthreads();

    int ty2 = tid >> 3, tx2 = tid & 7;
    int rr = ty2 * 4, cc = tx2 * 8;
    ull acc2[4][4];
#pragma unroll
    for (int i = 0; i < 4; i++)
#pragma unroll
        for (int p = 0; p < 4; p++) acc2[i][p] = 0ull;

    for (int k = 0; k < 128; k += 4) {
        float ac[4][4];
#pragma unroll
        for (int i = 0; i < 4; i++) {
            float4 a4 = *(const float4*)(sm + (rr + i) * 128 + k);
            ac[i][0] = a4.x; ac[i][1] = a4.y; ac[i][2] = a4.z; ac[i][3] = a4.w;
        }
#pragma unroll
        for (int kk = 0; kk < 4; kk++) {
            ulonglong2 q0 = *(const ulonglong2*)(W2s + (k + kk) * 64 + cc);
            ulonglong2 q1 = *(const ulonglong2*)(W2s + (k + kk) * 64 + cc + 4);
#pragma unroll
            for (int i = 0; i < 4; i++) {
                ull ad = dup2(ac[i][kk]);
                ffma2(acc2[i][0], ad, q0.x);
                ffma2(acc2[i][1], ad, q0.y);
                ffma2(acc2[i][2], ad, q1.x);
                ffma2(acc2[i][3], ad, q1.y);
            }
        }
    }
    float b2v[8];
#pragma unroll
    for (int j = 0; j < 8; j++) b2v[j] = b2[cc + j];
#pragma unroll
    for (int i = 0; i < 4; i++) {
        int node = block0 + rr + i;
        if (node < N_NODES) {
            float2 u0 = unpk(acc2[i][0]), u1 = unpk(acc2[i][1]);
            float2 u2 = unpk(acc2[i][2]), u3 = unpk(acc2[i][3]);
            float4 f0, f1;
            f0.x = fmaxf(u0.x + b2v[0], 0.f); f0.y = fmaxf(u0.y + b2v[1], 0.f);
            f0.z = fmaxf(u1.x + b2v[2], 0.f); f0.w = fmaxf(u1.y + b2v[3], 0.f);
            f1.x = fmaxf(u2.x + b2v[4], 0.f); f1.y = fmaxf(u2.y + b2v[5], 0.f);
            f1.z = fmaxf(u3.x + b2v[6], 0.f); f1.w = fmaxf(u3.y + b2v[7], 0.f);
            if (!last) {
                float* hp = g_h + (size_t)node * 64 + cc;
                *(float4*)hp = f0;
                *(float4*)(hp + 4) = f1;
                __half2 q0h = __floats2half2_rn(f0.x, f0.y);
                __half2 q1h = __floats2half2_rn(f0.z, f0.w);
                __half2 q2h = __floats2half2_rn(f1.x, f1.y);
                __half2 q3h = __floats2half2_rn(f1.z, f1.w);
                uint4 hv;
                hv.x = *(unsigned*)&q0h; hv.y = *(unsigned*)&q1h;
                hv.z = *(unsigned*)&q2h; hv.w = *(unsigned*)&q3h;
                *(uint4*)(g_h16 + (size_t)node * 64 + cc) = hv;
            } else {
                int g = __ldg(&batch[node]);
                float* pp = g_pool + g * 64 + cc;
                atomicAdd(pp + 0, f0.x); atomicAdd(pp + 1, f0.y);
                atomicAdd(pp + 2, f0.z); atomicAdd(pp + 3, f0.w);
                atomicAdd(pp + 4, f1.x); atomicAdd(pp + 5, f1.y);
                atomicAdd(pp + 6, f1.z); atomicAdd(pp + 7, f1.w);
            }
        }
    }
}

// ---------------- head: cnt via binary search on sorted batch ----------------
__global__ void k_head(const float* __restrict__ gattr,
                       const int* __restrict__ batch,
                       const float* __restrict__ d1W, const float* __restrict__ d1b,
                       const float* __restrict__ d2W, const float* __restrict__ d2b,
                       const float* __restrict__ oW, const float* __restrict__ ob,
                       float* __restrict__ out) {
    int g = blockIdx.x;
    int lane = threadIdx.x;
    __shared__ float gv[80];
    __shared__ float h1[32];
    __shared__ float h2s[32];
    int lb = 0;
    if (lane < 2) {
        int target = g + lane;
        int lo = 0, hi = N_NODES;
        while (lo < hi) {
            int mid = (lo + hi) >> 1;
            if (__ldg(&batch[mid]) < target) lo = mid + 1; else hi = mid;
        }
        lb = lo;
    }
    int cb = __shfl_sync(0xffffffffu, lb, 0);
    int ce = __shfl_sync(0xffffffffu, lb, 1);
    float inv = rcpf(fmaxf((float)(ce - cb), 1.0f));
    gv[lane] = g_pool[g * 64 + lane] * inv;
    gv[32 + lane] = g_pool[g * 64 + 32 + lane] * inv;
    if (lane < 10) gv[64 + lane] = gattr[g * 10 + lane];
    __syncwarp();
    float acc = d1b[lane];
#pragma unroll
    for (int k = 0; k < 74; k++) acc = fmaf(gv[k], d1W[k * 32 + lane], acc);
    h1[lane] = fmaxf(acc, 0.f);
    __syncwarp();
    acc = d2b[lane];
#pragma unroll
    for (int k = 0; k < 32; k++) acc = fmaf(h1[k], d2W[k * 32 + lane], acc);
    h2s[lane] = fmaxf(acc, 0.f);
    __syncwarp();
    float p = h2s[lane] * oW[lane];
    for (int o = 16; o; o >>= 1) p += __shfl_down_sync(0xffffffffu, p, o);
    if (lane == 0) {
        float z = p + ob[0];
        out[g] = rcpf(1.0f + ex2f(-z * L2E));
    }
}

// ---------------- launcher ----------------
extern "C" void kernel_launch(void* const* d_in, const int* in_sizes, int n_in,
                              void* d_out, int out_size) {
    const float* ord[25];
    const int* edge_index = nullptr;
    const int* batch = nullptr;
    int w = 0;
    for (int i = 0; i < n_in; i++) {
        if (in_sizes[i] == 2 * N_EDGES) edge_index = (const int*)d_in[i];
        else if (in_sizes[i] == N_NODES) batch = (const int*)d_in[i];
        else if (w < 25) ord[w++] = (const float*)d_in[i];
    }
    const float* x        = ord[0];
    const float* edge_at  = ord[1];
    const float* gattr    = ord[2];
    const float* node_W   = ord[3];
    const float* node_b   = ord[4];
    const float* edge_W   = ord[5];
    const float* edge_b   = ord[6];
    const float* cW1[3]   = {ord[7],  ord[11], ord[15]};
    const float* cb1[3]   = {ord[8],  ord[12], ord[16]};
    const float* cW2[3]   = {ord[9],  ord[13], ord[17]};
    const float* cb2[3]   = {ord[10], ord[14], ord[18]};
    const float* d1W = ord[19]; const float* d1b = ord[20];
    const float* d2W = ord[21]; const float* d2b = ord[22];
    const float* oW  = ord[23]; const float* ob  = ord[24];

    cudaFuncSetAttribute(k_mlp, cudaFuncAttributeMaxDynamicSharedMemorySize, 98304);

    k_node_lin<<<(N_NODES + 7) / 8, 256>>>(x, node_W, node_b, edge_index); // 1
    k_scan<<<NB_SCAN, 1024>>>();                                           // 2
    k_scatter<<<N_EDGES / 256, 256>>>(edge_index, edge_at, edge_W, edge_b); // 3

    for (int c = 0; c < 3; c++) {
        k_conv<<<(N_NODES + 7) / 8, 256>>>();   // 4 on first iter = profiled
        k_mlp<<<(N_NODES + 127) / 128, 256, 98304>>>(cW1[c], cb1[c], cW2[c], cb2[c],
                                                     batch, c == 2);
    }

    k_head<<<N_GRAPHS, 32>>>(gattr, batch, d1W, d1b, d2W, d2b, oW, ob, (float*)d_out);
    (void)out_size;
}